// round 4
// baseline (speedup 1.0000x reference)
#include <cuda_runtime.h>
#include <cstdint>

#define HH 1024
#define WW 1024
#define XV 4      // output pixels per thread (one float4 store)
#define RWS 16    // output rows per thread strip

__constant__ float cfilt[25];

// Load 8-float window v = input cols x0-2 .. x0+5 of row y (inf-padded).
__device__ __forceinline__ void load_row8(float* v, const float* __restrict__ ip,
                                          int y, int x0, bool interior) {
    const float INFv = __int_as_float(0x7f800000);
    if (y < 0 || y >= HH) {
#pragma unroll
        for (int m = 0; m < 8; ++m) v[m] = INFv;
    } else if (interior) {
        const float* base = ip + (size_t)y * WW + x0;
        float2 p0 = *reinterpret_cast<const float2*>(base - 2);
        float4 p1 = *reinterpret_cast<const float4*>(base);
        float2 p2 = *reinterpret_cast<const float2*>(base + 4);
        v[0] = p0.x; v[1] = p0.y;
        v[2] = p1.x; v[3] = p1.y; v[4] = p1.z; v[5] = p1.w;
        v[6] = p2.x; v[7] = p2.y;
    } else {
        const float* base = ip + (size_t)y * WW;
#pragma unroll
        for (int m = 0; m < 8; ++m) {
            int col = x0 - 2 + m;
            v[m] = (col >= 0 && col < WW) ? base[col] : INFv;
        }
    }
}

__global__ __launch_bounds__(128, 9)
void erosion5x5_f32_kernel(const float* __restrict__ img,
                           float* __restrict__ out) {
    const int x0 = (blockIdx.x * blockDim.x + threadIdx.x) * XV;
    const int y0 = blockIdx.y * RWS;
    const size_t plane = (size_t)blockIdx.z * (size_t)HH * (size_t)WW;
    const float* ip = img + plane;
    float* op = out + plane;

    const bool interior = (x0 >= 2) && (x0 + 6 <= WW);

    // Rolling 5-row window: slot k%5 holds input row y0+k-2 (full unroll -> static indexing)
    float W[5][8];
#pragma unroll
    for (int k = 0; k < 4; ++k)
        load_row8(W[k], ip, y0 + k - 2, x0, interior);

#pragma unroll
    for (int r = 0; r < RWS; ++r) {
        // Fresh row feeds tap row i=4, which is consumed last -> latency slack
        load_row8(W[(r + 4) % 5], ip, y0 + r + 2, x0, interior);

        // Two interleaved min-chains per pixel (even taps -> a0, odd -> a1):
        // 8 independent FMNMX chains per thread, depth ~12 instead of ~24.
        float a0[XV], a1[XV];
#pragma unroll
        for (int t = 0; t < 25; ++t) {
            const int i = t / 5;
            const int j = t % 5;
            const float f = cfilt[t];                    // LDCU -> UR operand
            const float* R = W[(r + i) % 5];             // input row y0+r+i-2
            if (t == 0) {
#pragma unroll
                for (int c = 0; c < XV; ++c) a0[c] = R[c + j] - f;
            } else if (t == 1) {
#pragma unroll
                for (int c = 0; c < XV; ++c) a1[c] = R[c + j] - f;
            } else if ((t & 1) == 0) {
#pragma unroll
                for (int c = 0; c < XV; ++c) a0[c] = fminf(a0[c], R[c + j] - f);
            } else {
#pragma unroll
                for (int c = 0; c < XV; ++c) a1[c] = fminf(a1[c], R[c + j] - f);
            }
        }

        float4 o;
        o.x = fminf(a0[0], a1[0]);
        o.y = fminf(a0[1], a1[1]);
        o.z = fminf(a0[2], a1[2]);
        o.w = fminf(a0[3], a1[3]);
        *reinterpret_cast<float4*>(op + (size_t)(y0 + r) * WW + x0) = o;
    }
}

extern "C" void kernel_launch(void* const* d_in, const int* in_sizes, int n_in,
                              void* d_out, int out_size) {
    const float* image = (const float*)d_in[0];
    const float* filt  = (const float*)d_in[1];
    float* out = (float*)d_out;

    // Filter -> constant bank (async D2D copy; graph-capturable memcpy node)
    cudaMemcpyToSymbolAsync(cfilt, filt, 25 * sizeof(float), 0,
                            cudaMemcpyDeviceToDevice, 0);

    const int planes = in_sizes[0] / (HH * WW);  // 32*3 = 96

    dim3 block(128, 1, 1);
    dim3 grid(WW / (128 * XV), HH / RWS, planes);  // (2, 64, 96)
    erosion5x5_f32_kernel<<<grid, block>>>(image, out);
}